// round 16
// baseline (speedup 1.0000x reference)
#include <cuda_runtime.h>
#include <math.h>

// Combined per-interval cubic: f(x) ≈ ((P.x*u+P.y)*u+P.z)*u+P.w,
// u = 13x - j, j = clamp(floor(13x), 3, 9). P folds ws*spline (exact) and
// wb*silu (per-interval cubic Chebyshev fit, err ~6e-6).

// ---------------------------------------------------------------------------
// In-kernel table build, pure fp32 (threads 0..6; ~60 instrs).
// ---------------------------------------------------------------------------
__device__ __forceinline__ void build_poly_smem(float4* sPoly,
                                                const float* __restrict__ coef,
                                                const float* __restrict__ wbp,
                                                const float* __restrict__ wsp) {
    int iv = threadIdx.x;            // 0..6 -> knot interval j = iv+3
    if (iv < 7) {
        float wb = __ldg(wbp);
        float ws = __ldg(wsp);
        int i = iv + 3;

        // exact uniform cubic B-spline segment, monomial in u
        float c0 = __ldg(coef + iv + 0);
        float c1 = __ldg(coef + iv + 1);
        float c2 = __ldg(coef + iv + 2);
        float c3 = __ldg(coef + iv + 3);
        const float s = 1.0f / 6.0f;
        float sa = (-c0 + 3.0f * c1 - 3.0f * c2 + c3) * s;
        float sb = ( 3.0f * c0 - 6.0f * c1 + 3.0f * c2) * s;
        float sc = (-3.0f * c0 + 3.0f * c2) * s;
        float sd = ( c0 + 4.0f * c1 + c2) * s;

        // cubic Chebyshev fit of silu over this interval's served u-range
        float ulo = (iv == 0) ? -3.0f : 0.0f;
        float uhi = (iv == 6) ?  4.0f : 1.0f;
        float mid = 0.5f * (ulo + uhi), rad = 0.5f * (uhi - ulo);
        const float cn0 =  0.92387953f, cn1 = 0.38268343f;
        float un[4], fv[4];
        un[0] = mid + rad * cn0;
        un[1] = mid + rad * cn1;
        un[2] = mid - rad * cn1;
        un[3] = mid - rad * cn0;
        #pragma unroll
        for (int k = 0; k < 4; k++) {
            float xx = (un[k] + (float)i) * (1.0f / 13.0f);
            fv[k] = xx / (1.0f + __expf(-xx));          // silu(xx)
        }
        float d0    = fv[0];
        float d01   = (fv[1] - fv[0]) / (un[1] - un[0]);
        float d12   = (fv[2] - fv[1]) / (un[2] - un[1]);
        float d23   = (fv[3] - fv[2]) / (un[3] - un[2]);
        float d012  = (d12 - d01) / (un[2] - un[0]);
        float d123  = (d23 - d12) / (un[3] - un[1]);
        float d0123 = (d123 - d012) / (un[3] - un[0]);
        float e0 = un[0] + un[1], e01 = un[0] * un[1];
        float A3 = d0123;
        float A2 = d012 - d0123 * (un[0] + un[1] + un[2]);
        float A1 = d01 - d012 * e0 + d0123 * (e01 + un[0] * un[2] + un[1] * un[2]);
        float A0 = d0 - d01 * un[0] + d012 * e01 - d0123 * e01 * un[2];

        float4 p;
        p.x = fmaf(ws, sa, wb * A3);
        p.y = fmaf(ws, sb, wb * A2);
        p.z = fmaf(ws, sc, wb * A1);
        p.w = fmaf(ws, sd, wb * A0);
        sPoly[iv] = p;
    }
}

__device__ __forceinline__ float eval_one(float x, const float4* __restrict__ sPoly) {
    float fi = x * 13.0f;
    // clamp in FLOAT domain: truncf + 2 FMNMX ride the (lighter) fma pipe
    float jf = truncf(fi);                 // x >= 0: trunc == floor
    jf = fminf(fmaxf(jf, 3.0f), 9.0f);     // scipy clip -> poly extrapolation
    float u = fi - jf;
    int j = (int)jf;                       // exact small integer
    float4 p = sPoly[j - 3];               // 7x16B: distinct banks + broadcast dedup
    return fmaf(fmaf(fmaf(p.x, u, p.y), u, p.z), u, p.w);
}

// Register-free L2 prefetch of a global address.
__device__ __forceinline__ void prefetch_l2(const void* p) {
    asm volatile("prefetch.global.L2 [%0];" :: "l"(p));
}

#define V_PER_THREAD 4   // float4s per thread per loop iteration (64 B)

__global__ void __launch_bounds__(256, 8)
residual_act_fused_kernel(const float4* __restrict__ x4,
                          float4* __restrict__ out4,
                          int n4,
                          const float* __restrict__ xs,   // scalar view for tail
                          float* __restrict__ outs,       // scalar view for tail
                          int n,
                          const float* __restrict__ coef,
                          const float* __restrict__ wbp,
                          const float* __restrict__ wsp) {
    __shared__ float4 sPoly[7];
    build_poly_smem(sPoly, coef, wbp, wsp);
    __syncthreads();

    const int tile   = 256 * V_PER_THREAD;        // float4s per block-iter
    const int stride = gridDim.x * tile;

    for (int base0 = blockIdx.x * tile; base0 < n4; base0 += stride) {
        int base = base0 + threadIdx.x;
        if (base0 + tile <= n4) {
            float4 xv[V_PER_THREAD];
            #pragma unroll
            for (int k = 0; k < V_PER_THREAD; k++)
                xv[k] = x4[base + k * 256];

            // Register-free prefetch of NEXT tile into L2 while we compute.
            int nb0 = base0 + stride;
            if (nb0 < n4) {
                int nb = base + stride;
                #pragma unroll
                for (int k = 0; k < V_PER_THREAD; k++)
                    prefetch_l2(x4 + nb + k * 256);
            }

            #pragma unroll
            for (int k = 0; k < V_PER_THREAD; k++) {
                float4 ov;
                ov.x = eval_one(xv[k].x, sPoly);
                ov.y = eval_one(xv[k].y, sPoly);
                ov.z = eval_one(xv[k].z, sPoly);
                ov.w = eval_one(xv[k].w, sPoly);
                // streaming store: evict-first so output doesn't evict x from L2
                __stcs(out4 + base + k * 256, ov);
            }
        } else {
            #pragma unroll
            for (int k = 0; k < V_PER_THREAD; k++) {
                int idx = base + k * 256;
                if (idx < n4) {
                    float4 xv = x4[idx];
                    float4 ov;
                    ov.x = eval_one(xv.x, sPoly);
                    ov.y = eval_one(xv.y, sPoly);
                    ov.z = eval_one(xv.z, sPoly);
                    ov.w = eval_one(xv.w, sPoly);
                    __stcs(out4 + idx, ov);
                }
            }
        }
    }

    // In-kernel scalar tail for n % 4 != 0 (never taken for n = 2^24).
    int tail_start = n4 * 4;
    if (blockIdx.x == 0) {
        for (int idx = tail_start + threadIdx.x; idx < n; idx += 256) {
            outs[idx] = eval_one(xs[idx], sPoly);
        }
    }
}

extern "C" void kernel_launch(void* const* d_in, const int* in_sizes, int n_in,
                              void* d_out, int out_size) {
    const float* x    = (const float*)d_in[0];   // [N] activations
    const float* coef = (const float*)d_in[1];   // [10] spline coefficients
    const float* wb   = (const float*)d_in[2];   // [1] w_basis
    const float* ws   = (const float*)d_in[3];   // [1] w_spline
    float* out        = (float*)d_out;

    int n  = in_sizes[0];
    int n4 = n / 4;

    const int tile = 256 * V_PER_THREAD;
    int work_blocks = (n4 + tile - 1) / tile;
    if (work_blocks < 1) work_blocks = 1;        // tail-only degenerate case
    // Balanced persistent grid: every block runs exactly `iters` tiles.
    // (4096 tiles -> iters=4 -> 1024 blocks; single resident wave, no straggler)
    int cap   = 1184;
    int iters = (work_blocks + cap - 1) / cap;
    int blocks = (work_blocks + iters - 1) / iters;
    residual_act_fused_kernel<<<blocks, 256>>>(
        (const float4*)x, (float4*)out, n4, x, out, n, coef, wb, ws);
}

// round 17
// speedup vs baseline: 1.0156x; 1.0156x over previous
#include <cuda_runtime.h>
#include <math.h>

// Combined per-interval cubic: f(x) ≈ ((P.x*u+P.y)*u+P.z)*u+P.w,
// u = 13x - j, j = clamp(floor(13x), 3, 9). P folds ws*spline (exact) and
// wb*silu (per-interval cubic Chebyshev fit, err ~6e-6).

// ---------------------------------------------------------------------------
// In-kernel table build, pure fp32 (threads 0..6; ~60 instrs).
// ---------------------------------------------------------------------------
__device__ __forceinline__ void build_poly_smem(float4* sPoly,
                                                const float* __restrict__ coef,
                                                const float* __restrict__ wbp,
                                                const float* __restrict__ wsp) {
    int iv = threadIdx.x;            // 0..6 -> knot interval j = iv+3
    if (iv < 7) {
        float wb = __ldg(wbp);
        float ws = __ldg(wsp);
        int i = iv + 3;

        // exact uniform cubic B-spline segment, monomial in u
        float c0 = __ldg(coef + iv + 0);
        float c1 = __ldg(coef + iv + 1);
        float c2 = __ldg(coef + iv + 2);
        float c3 = __ldg(coef + iv + 3);
        const float s = 1.0f / 6.0f;
        float sa = (-c0 + 3.0f * c1 - 3.0f * c2 + c3) * s;
        float sb = ( 3.0f * c0 - 6.0f * c1 + 3.0f * c2) * s;
        float sc = (-3.0f * c0 + 3.0f * c2) * s;
        float sd = ( c0 + 4.0f * c1 + c2) * s;

        // cubic Chebyshev fit of silu over this interval's served u-range
        float ulo = (iv == 0) ? -3.0f : 0.0f;
        float uhi = (iv == 6) ?  4.0f : 1.0f;
        float mid = 0.5f * (ulo + uhi), rad = 0.5f * (uhi - ulo);
        const float cn0 =  0.92387953f, cn1 = 0.38268343f;
        float un[4], fv[4];
        un[0] = mid + rad * cn0;
        un[1] = mid + rad * cn1;
        un[2] = mid - rad * cn1;
        un[3] = mid - rad * cn0;
        #pragma unroll
        for (int k = 0; k < 4; k++) {
            float xx = (un[k] + (float)i) * (1.0f / 13.0f);
            fv[k] = xx / (1.0f + __expf(-xx));          // silu(xx)
        }
        float d0    = fv[0];
        float d01   = (fv[1] - fv[0]) / (un[1] - un[0]);
        float d12   = (fv[2] - fv[1]) / (un[2] - un[1]);
        float d23   = (fv[3] - fv[2]) / (un[3] - un[2]);
        float d012  = (d12 - d01) / (un[2] - un[0]);
        float d123  = (d23 - d12) / (un[3] - un[1]);
        float d0123 = (d123 - d012) / (un[3] - un[0]);
        float e0 = un[0] + un[1], e01 = un[0] * un[1];
        float A3 = d0123;
        float A2 = d012 - d0123 * (un[0] + un[1] + un[2]);
        float A1 = d01 - d012 * e0 + d0123 * (e01 + un[0] * un[2] + un[1] * un[2]);
        float A0 = d0 - d01 * un[0] + d012 * e01 - d0123 * e01 * un[2];

        float4 p;
        p.x = fmaf(ws, sa, wb * A3);
        p.y = fmaf(ws, sb, wb * A2);
        p.z = fmaf(ws, sc, wb * A1);
        p.w = fmaf(ws, sd, wb * A0);
        sPoly[iv] = p;
    }
}

__device__ __forceinline__ float eval_one(float x, const float4* __restrict__ sPoly) {
    float fi = x * 13.0f;
    // clamp in FLOAT domain: truncf + 2 FMNMX ride the (lighter) fma pipe
    float jf = truncf(fi);                 // x >= 0: trunc == floor
    jf = fminf(fmaxf(jf, 3.0f), 9.0f);     // scipy clip -> poly extrapolation
    float u = fi - jf;
    int j = (int)jf;                       // exact small integer
    float4 p = sPoly[j - 3];               // 7x16B: distinct banks + broadcast dedup
    return fmaf(fmaf(fmaf(p.x, u, p.y), u, p.z), u, p.w);
}

#define V_PER_THREAD 4   // float4s per thread per loop iteration (64 B)

__global__ void __launch_bounds__(256, 8)
residual_act_fused_kernel(const float4* __restrict__ x4,
                          float4* __restrict__ out4,
                          int n4,
                          const float* __restrict__ xs,   // scalar view for tail
                          float* __restrict__ outs,       // scalar view for tail
                          int n,
                          const float* __restrict__ coef,
                          const float* __restrict__ wbp,
                          const float* __restrict__ wsp) {
    __shared__ float4 sPoly[7];
    build_poly_smem(sPoly, coef, wbp, wsp);
    __syncthreads();

    const int tile = 256 * V_PER_THREAD;          // float4s per block-iter
    for (int base0 = blockIdx.x * tile; base0 < n4; base0 += gridDim.x * tile) {
        int base = base0 + threadIdx.x;
        if (base0 + tile <= n4) {
            float4 xv[V_PER_THREAD];
            #pragma unroll
            for (int k = 0; k < V_PER_THREAD; k++)
                xv[k] = x4[base + k * 256];
            #pragma unroll
            for (int k = 0; k < V_PER_THREAD; k++) {
                float4 ov;
                ov.x = eval_one(xv[k].x, sPoly);
                ov.y = eval_one(xv[k].y, sPoly);
                ov.z = eval_one(xv[k].z, sPoly);
                ov.w = eval_one(xv[k].w, sPoly);
                // streaming store: evict-first so output doesn't evict x from L2
                __stcs(out4 + base + k * 256, ov);
            }
        } else {
            #pragma unroll
            for (int k = 0; k < V_PER_THREAD; k++) {
                int idx = base + k * 256;
                if (idx < n4) {
                    float4 xv = x4[idx];
                    float4 ov;
                    ov.x = eval_one(xv.x, sPoly);
                    ov.y = eval_one(xv.y, sPoly);
                    ov.z = eval_one(xv.z, sPoly);
                    ov.w = eval_one(xv.w, sPoly);
                    __stcs(out4 + idx, ov);
                }
            }
        }
    }

    // In-kernel scalar tail for n % 4 != 0 (never taken for n = 2^24).
    int tail_start = n4 * 4;
    if (blockIdx.x == 0) {
        for (int idx = tail_start + threadIdx.x; idx < n; idx += 256) {
            outs[idx] = eval_one(xs[idx], sPoly);
        }
    }
}

extern "C" void kernel_launch(void* const* d_in, const int* in_sizes, int n_in,
                              void* d_out, int out_size) {
    const float* x    = (const float*)d_in[0];   // [N] activations
    const float* coef = (const float*)d_in[1];   // [10] spline coefficients
    const float* wb   = (const float*)d_in[2];   // [1] w_basis
    const float* ws   = (const float*)d_in[3];   // [1] w_spline
    float* out        = (float*)d_out;

    int n  = in_sizes[0];
    int n4 = n / 4;

    const int tile = 256 * V_PER_THREAD;
    int work_blocks = (n4 + tile - 1) / tile;
    if (work_blocks < 1) work_blocks = 1;        // tail-only degenerate case
    // Balanced persistent grid: every block runs exactly `iters` tiles.
    // (4096 tiles -> iters=4 -> 1024 blocks; single resident wave, no straggler)
    int cap   = 1184;
    int iters = (work_blocks + cap - 1) / cap;
    int blocks = (work_blocks + iters - 1) / iters;
    residual_act_fused_kernel<<<blocks, 256>>>(
        (const float4*)x, (float4*)out, n4, x, out, n, coef, wb, ws);
}